// round 13
// baseline (speedup 1.0000x reference)
#include <cuda_runtime.h>
#include <cstdint>

// TaylorActivation: out = Horner(x; c[0..8]), elementwise over 512x65536 fp32.
// HBM/LTS-bound stream: 128 MiB in + 128 MiB out.
//
// R10: persistent grid-stride (148 SMs x 8 CTAs = 1184 blocks, ~7 iters each)
//      to eliminate CTA churn / wave transitions, + FFMA2 packed Horner (R9),
//      4x float4 front-batched loads per iteration.

__device__ __forceinline__ uint64_t pack2(float lo, float hi) {
    uint64_t r;
    asm("mov.b64 %0, {%1, %2};" : "=l"(r) : "f"(lo), "f"(hi));
    return r;
}

__device__ __forceinline__ void unpack2(uint64_t v, float& lo, float& hi) {
    asm("mov.b64 {%0, %1}, %2;" : "=f"(lo), "=f"(hi) : "l"(v));
}

__device__ __forceinline__ uint64_t fma2(uint64_t a, uint64_t b, uint64_t c) {
    uint64_t d;
    asm("fma.rn.f32x2 %0, %1, %2, %3;" : "=l"(d) : "l"(a), "l"(b), "l"(c));
    return d;
}

#define NBLOCKS 1184   // 148 SMs * 8 CTAs
#define NTHREADS 256
#define F4_PER_ITER (NTHREADS * 4)   // 1024 float4 per CTA-iteration

__global__ void __launch_bounds__(NTHREADS)
taylor_kernel(const float4* __restrict__ x,
              const float* __restrict__ w,
              float4* __restrict__ out,
              int n4)
{
    // Coefficients: once per thread for the CTA's whole lifetime.
    const float4 wa = __ldg((const float4*)&w[0]);  // c0..c3
    const float4 wb = __ldg((const float4*)&w[4]);  // c4..c7
    const float  c8 = __ldg(&w[8]);

    const uint64_t p0 = pack2(wa.x, wa.x), p1 = pack2(wa.y, wa.y);
    const uint64_t p2 = pack2(wa.z, wa.z), p3 = pack2(wa.w, wa.w);
    const uint64_t p4 = pack2(wb.x, wb.x), p5 = pack2(wb.y, wb.y);
    const uint64_t p6 = pack2(wb.z, wb.z), p7 = pack2(wb.w, wb.w);
    const uint64_t p8 = pack2(c8, c8);

    const int stride = NBLOCKS * F4_PER_ITER;
    int base = blockIdx.x * F4_PER_ITER + threadIdx.x;

#pragma unroll 1
    for (; base + 3 * NTHREADS < n4; base += stride) {
        // Front-batched independent loads (MLP_p1 = 4).
        float4 v0 = x[base + 0 * NTHREADS];
        float4 v1 = x[base + 1 * NTHREADS];
        float4 v2 = x[base + 2 * NTHREADS];
        float4 v3 = x[base + 3 * NTHREADS];

        uint64_t a0 = pack2(v0.x, v0.y), b0 = pack2(v0.z, v0.w);
        uint64_t a1 = pack2(v1.x, v1.y), b1 = pack2(v1.z, v1.w);
        uint64_t a2 = pack2(v2.x, v2.y), b2 = pack2(v2.z, v2.w);
        uint64_t a3 = pack2(v3.x, v3.y), b3 = pack2(v3.z, v3.w);

        uint64_t ra0 = p8, rb0 = p8;
        uint64_t ra1 = p8, rb1 = p8;
        uint64_t ra2 = p8, rb2 = p8;
        uint64_t ra3 = p8, rb3 = p8;

#define STEP(pk)                                          \
        ra0 = fma2(ra0, a0, pk); rb0 = fma2(rb0, b0, pk); \
        ra1 = fma2(ra1, a1, pk); rb1 = fma2(rb1, b1, pk); \
        ra2 = fma2(ra2, a2, pk); rb2 = fma2(rb2, b2, pk); \
        ra3 = fma2(ra3, a3, pk); rb3 = fma2(rb3, b3, pk);

        STEP(p7) STEP(p6) STEP(p5) STEP(p4)
        STEP(p3) STEP(p2) STEP(p1) STEP(p0)
#undef STEP

        float4 r;
        unpack2(ra0, r.x, r.y); unpack2(rb0, r.z, r.w); out[base + 0 * NTHREADS] = r;
        unpack2(ra1, r.x, r.y); unpack2(rb1, r.z, r.w); out[base + 1 * NTHREADS] = r;
        unpack2(ra2, r.x, r.y); unpack2(rb2, r.z, r.w); out[base + 2 * NTHREADS] = r;
        unpack2(ra3, r.x, r.y); unpack2(rb3, r.z, r.w); out[base + 3 * NTHREADS] = r;
    }
    // n4 = 8388608 = 8192 * 1024 tiles; every tile is full, so no scalar tail
    // is needed: the loop condition covers exactly the full range.
}

extern "C" void kernel_launch(void* const* d_in, const int* in_sizes, int n_in,
                              void* d_out, int out_size)
{
    const float* x = (const float*)d_in[0];   // (512, 65536) fp32
    const float* w = (const float*)d_in[1];   // (9, 1) fp32
    float* out = (float*)d_out;

    int n = in_sizes[0];          // 33554432
    int n4 = n / 4;               // 8388608 float4 (= 8192 tiles of 1024)

    taylor_kernel<<<NBLOCKS, NTHREADS>>>(
        (const float4*)x, w, (float4*)out, n4);
}

// round 14
// speedup vs baseline: 1.0949x; 1.0949x over previous
#include <cuda_runtime.h>
#include <cstdint>

// TaylorActivation: out = Horner(x; c[0..8]), elementwise over 512x65536 fp32.
// HBM/LTS-bound stream: 128 MiB in + 128 MiB out.
//
// R13: 2x float4/thread (16384 blocks x 256 thr) — shorter CTA lifetime,
//      less cross-CTA L1tex queue contention; FFMA2 packed Horner (R9),
//      3 vectorized broadcast coeff LDGs, default cache ops, 1 graph node.

__device__ __forceinline__ uint64_t pack2(float lo, float hi) {
    uint64_t r;
    asm("mov.b64 %0, {%1, %2};" : "=l"(r) : "f"(lo), "f"(hi));
    return r;
}

__device__ __forceinline__ void unpack2(uint64_t v, float& lo, float& hi) {
    asm("mov.b64 {%0, %1}, %2;" : "=f"(lo), "=f"(hi) : "l"(v));
}

__device__ __forceinline__ uint64_t fma2(uint64_t a, uint64_t b, uint64_t c) {
    uint64_t d;
    asm("fma.rn.f32x2 %0, %1, %2, %3;" : "=l"(d) : "l"(a), "l"(b), "l"(c));
    return d;
}

__global__ void __launch_bounds__(256)
taylor_kernel(const float4* __restrict__ x,
              const float* __restrict__ w,
              float4* __restrict__ out)
{
    int base = blockIdx.x * (256 * 2) + threadIdx.x;

    // Front-batched independent loads (MLP_p1 = 2 per thread; 2x warps vs R9).
    float4 v0 = x[base + 0 * 256];
    float4 v1 = x[base + 1 * 256];

    // 9 coefficients via 3 broadcast loads (L1-resident after first warp).
    const float4 wa = __ldg((const float4*)&w[0]);  // c0..c3
    const float4 wb = __ldg((const float4*)&w[4]);  // c4..c7
    const float  c8 = __ldg(&w[8]);

    const uint64_t p0 = pack2(wa.x, wa.x), p1 = pack2(wa.y, wa.y);
    const uint64_t p2 = pack2(wa.z, wa.z), p3 = pack2(wa.w, wa.w);
    const uint64_t p4 = pack2(wb.x, wb.x), p5 = pack2(wb.y, wb.y);
    const uint64_t p6 = pack2(wb.z, wb.z), p7 = pack2(wb.w, wb.w);
    const uint64_t p8 = pack2(c8, c8);

    uint64_t a0 = pack2(v0.x, v0.y), b0 = pack2(v0.z, v0.w);
    uint64_t a1 = pack2(v1.x, v1.y), b1 = pack2(v1.z, v1.w);

    uint64_t ra0 = p8, rb0 = p8;
    uint64_t ra1 = p8, rb1 = p8;

#define STEP(pk)                                      \
    ra0 = fma2(ra0, a0, pk); rb0 = fma2(rb0, b0, pk); \
    ra1 = fma2(ra1, a1, pk); rb1 = fma2(rb1, b1, pk);

    STEP(p7) STEP(p6) STEP(p5) STEP(p4)
    STEP(p3) STEP(p2) STEP(p1) STEP(p0)
#undef STEP

    float4 r;
    unpack2(ra0, r.x, r.y); unpack2(rb0, r.z, r.w); out[base + 0 * 256] = r;
    unpack2(ra1, r.x, r.y); unpack2(rb1, r.z, r.w); out[base + 1 * 256] = r;
}

extern "C" void kernel_launch(void* const* d_in, const int* in_sizes, int n_in,
                              void* d_out, int out_size)
{
    const float* x = (const float*)d_in[0];   // (512, 65536) fp32
    const float* w = (const float*)d_in[1];   // (9, 1) fp32
    float* out = (float*)d_out;

    int n = in_sizes[0];          // 33554432
    int n4 = n / 4;               // 8388608 float4
    int blocks = n4 / (256 * 2);  // 16384 (exact)

    taylor_kernel<<<blocks, 256>>>(
        (const float4*)x, w, (float4*)out);
}